// round 12
// baseline (speedup 1.0000x reference)
#include <cuda_runtime.h>
#include <cuda_bf16.h>
#include <cstdint>

// Problem shape (fixed by reference setup_inputs)
#define B_    16
#define C_    384
#define CR_   96
#define HW_   12544          // 112*112
#define HW4_  3136           // HW/4 (float4 per plane); 3136 = 448*7 exactly
#define NPLANES_ (B_ * C_)   // 6144
#define T_    448
#define K_    7

// Scratch (no cudaMalloc allowed) — device globals.
__device__ float g_mean[NPLANES_];
__device__ float g_t[B_ * CR_];
__device__ float g_scale[NPLANES_];

// ---------------------------------------------------------------------------
// Kernel 1: per-plane mean. One CTA per plane. At DRAM roofline (82-84%).
// Ascending plane order: the tail of x is the freshest content in L2 when
// this kernel ends.
// ---------------------------------------------------------------------------
__global__ void __launch_bounds__(T_) se_reduce_kernel(const float* __restrict__ x) {
    const int plane = blockIdx.x;
    const float4* __restrict__ p =
        reinterpret_cast<const float4*>(x) + (size_t)plane * HW4_;

    float4 v[K_];
    #pragma unroll
    for (int k = 0; k < K_; k++)
        v[k] = p[threadIdx.x + k * T_];

    float sum = 0.0f;
    #pragma unroll
    for (int k = 0; k < K_; k++)
        sum += (v[k].x + v[k].y) + (v[k].z + v[k].w);

    #pragma unroll
    for (int o = 16; o > 0; o >>= 1)
        sum += __shfl_down_sync(0xffffffffu, sum, o);

    __shared__ float sdata[T_ / 32];
    const int lane = threadIdx.x & 31;
    const int wid  = threadIdx.x >> 5;
    if (lane == 0) sdata[wid] = sum;
    __syncthreads();
    if (wid == 0) {
        sum = (lane < (T_ / 32)) ? sdata[lane] : 0.0f;
        #pragma unroll
        for (int o = 8; o > 0; o >>= 1)
            sum += __shfl_down_sync(0xffffffffu, sum, o);
        if (lane == 0) g_mean[plane] = sum * (1.0f / (float)HW_);
    }
}

// ---------------------------------------------------------------------------
// Kernel 2a: fc1 — one warp per (b,r) dot, no per-warp loop.
// ---------------------------------------------------------------------------
__global__ void __launch_bounds__(128) se_fc1_kernel(const float* __restrict__ w1,
                                                     const float* __restrict__ b1) {
    const int lane = threadIdx.x & 31;
    const int d    = blockIdx.x * 4 + (threadIdx.x >> 5);   // 0..1535
    const int b    = d / CR_;
    const int r    = d % CR_;

    const float4* __restrict__ wr4 =
        reinterpret_cast<const float4*>(w1 + r * C_);
    const float4* __restrict__ sb4 =
        reinterpret_cast<const float4*>(g_mean + b * C_);

    float acc = 0.0f;
    #pragma unroll
    for (int k = 0; k < 3; k++) {
        const int i4 = lane + 32 * k;
        const float4 wv = __ldg(&wr4[i4]);
        const float4 sv = sb4[i4];
        acc = fmaf(wv.x, sv.x, acc);
        acc = fmaf(wv.y, sv.y, acc);
        acc = fmaf(wv.z, sv.z, acc);
        acc = fmaf(wv.w, sv.w, acc);
    }
    #pragma unroll
    for (int o = 16; o > 0; o >>= 1)
        acc += __shfl_down_sync(0xffffffffu, acc, o);
    if (lane == 0) g_t[d] = fmaxf(acc + __ldg(&b1[r]), 0.0f);
}

// ---------------------------------------------------------------------------
// Kernel 2b: fc2 — one warp per (b,c) dot, no per-warp loop.
// ---------------------------------------------------------------------------
__global__ void __launch_bounds__(128) se_fc2_kernel(const float* __restrict__ w2,
                                                     const float* __restrict__ b2) {
    const int lane = threadIdx.x & 31;
    const int d    = blockIdx.x * 4 + (threadIdx.x >> 5);   // 0..6143
    const int b    = d / C_;
    const int c    = d % C_;

    const float* __restrict__ wc = w2 + c * CR_;
    const float* __restrict__ tb = g_t + b * CR_;

    float acc = 0.0f;
    #pragma unroll
    for (int k = 0; k < 3; k++) {
        const int r = lane + 32 * k;
        acc = fmaf(__ldg(&wc[r]), tb[r], acc);
    }
    #pragma unroll
    for (int o = 16; o > 0; o >>= 1)
        acc += __shfl_down_sync(0xffffffffu, acc, o);
    if (lane == 0)
        g_scale[b * C_ + c] =
            __saturatef(fmaf(acc + __ldg(&b2[c]), 1.0f / 6.0f, 0.5f));
}

// ---------------------------------------------------------------------------
// Kernel 3: broadcast multiply. Reverse plane order (L2-hot tail first).
// Loads: __ldcs (hit then evict-first). Stores: __stwt (write-through, NO L2
// allocation) so the 308MB write stream cannot evict the x-tail we are about
// to read. Output is never re-read, so write-allocate buys nothing.
// ---------------------------------------------------------------------------
__global__ void __launch_bounds__(T_) se_scale_kernel(const float* __restrict__ x,
                                                      float* __restrict__ out) {
    const int plane = (NPLANES_ - 1) - blockIdx.x;
    const float sc = g_scale[plane];
    const float4* __restrict__ p =
        reinterpret_cast<const float4*>(x) + (size_t)plane * HW4_;
    float4* __restrict__ o =
        reinterpret_cast<float4*>(out) + (size_t)plane * HW4_;

    float4 v[K_];
    #pragma unroll
    for (int k = 0; k < K_; k++)
        v[k] = __ldcs(&p[threadIdx.x + k * T_]);

    #pragma unroll
    for (int k = 0; k < K_; k++) {
        v[k].x *= sc; v[k].y *= sc; v[k].z *= sc; v[k].w *= sc;
        __stwt(&o[threadIdx.x + k * T_], v[k]);
    }
}

// ---------------------------------------------------------------------------
extern "C" void kernel_launch(void* const* d_in, const int* in_sizes, int n_in,
                              void* d_out, int out_size) {
    const float* x  = (const float*)d_in[0];
    const float* w1 = (const float*)d_in[1];
    const float* b1 = (const float*)d_in[2];
    const float* w2 = (const float*)d_in[3];
    const float* b2 = (const float*)d_in[4];
    float* out = (float*)d_out;

    se_reduce_kernel<<<NPLANES_, T_>>>(x);
    se_fc1_kernel<<<(B_ * CR_) / 4, 128>>>(w1, b1);
    se_fc2_kernel<<<(B_ * C_) / 4, 128>>>(w2, b2);
    se_scale_kernel<<<NPLANES_, T_>>>(x, out);
}

// round 13
// speedup vs baseline: 1.0235x; 1.0235x over previous
#include <cuda_runtime.h>
#include <cuda_bf16.h>
#include <cstdint>

// Problem shape (fixed by reference setup_inputs)
#define B_    16
#define C_    384
#define CR_   96
#define HW_   12544          // 112*112
#define HW4_  3136           // HW/4 (float4 per plane); 3136 = 448*7 exactly
#define NPLANES_ (B_ * C_)   // 6144
#define T_    448
#define K_    7

// Scratch (no cudaMalloc allowed) — device globals.
__device__ float g_mean[NPLANES_];
__device__ float g_t[B_ * CR_];

// ---------------------------------------------------------------------------
// Kernel 1: per-plane mean. One CTA per plane. At DRAM roofline (~83%).
// ---------------------------------------------------------------------------
__global__ void __launch_bounds__(T_) se_reduce_kernel(const float* __restrict__ x) {
    const int plane = blockIdx.x;
    const float4* __restrict__ p =
        reinterpret_cast<const float4*>(x) + (size_t)plane * HW4_;

    float4 v[K_];
    #pragma unroll
    for (int k = 0; k < K_; k++)
        v[k] = p[threadIdx.x + k * T_];

    float sum = 0.0f;
    #pragma unroll
    for (int k = 0; k < K_; k++)
        sum += (v[k].x + v[k].y) + (v[k].z + v[k].w);

    #pragma unroll
    for (int o = 16; o > 0; o >>= 1)
        sum += __shfl_down_sync(0xffffffffu, sum, o);

    __shared__ float sdata[T_ / 32];
    const int lane = threadIdx.x & 31;
    const int wid  = threadIdx.x >> 5;
    if (lane == 0) sdata[wid] = sum;
    __syncthreads();
    if (wid == 0) {
        sum = (lane < (T_ / 32)) ? sdata[lane] : 0.0f;
        #pragma unroll
        for (int o = 8; o > 0; o >>= 1)
            sum += __shfl_down_sync(0xffffffffu, sum, o);
        if (lane == 0) g_mean[plane] = sum * (1.0f / (float)HW_);
    }
}

// ---------------------------------------------------------------------------
// Kernel 2: fc1 — one warp per (b,r) dot, no per-warp loop. ~2us.
// ---------------------------------------------------------------------------
__global__ void __launch_bounds__(128) se_fc1_kernel(const float* __restrict__ w1,
                                                     const float* __restrict__ b1) {
    const int lane = threadIdx.x & 31;
    const int d    = blockIdx.x * 4 + (threadIdx.x >> 5);   // 0..1535
    const int b    = d / CR_;
    const int r    = d % CR_;

    const float4* __restrict__ wr4 =
        reinterpret_cast<const float4*>(w1 + r * C_);
    const float4* __restrict__ sb4 =
        reinterpret_cast<const float4*>(g_mean + b * C_);

    float acc = 0.0f;
    #pragma unroll
    for (int k = 0; k < 3; k++) {
        const int i4 = lane + 32 * k;
        const float4 wv = __ldg(&wr4[i4]);
        const float4 sv = sb4[i4];
        acc = fmaf(wv.x, sv.x, acc);
        acc = fmaf(wv.y, sv.y, acc);
        acc = fmaf(wv.z, sv.z, acc);
        acc = fmaf(wv.w, sv.w, acc);
    }
    #pragma unroll
    for (int o = 16; o > 0; o >>= 1)
        acc += __shfl_down_sync(0xffffffffu, acc, o);
    if (lane == 0) g_t[d] = fmaxf(acc + __ldg(&b1[r]), 0.0f);
}

// ---------------------------------------------------------------------------
// Kernel 3: fused fc2 + broadcast multiply.
// Each CTA: (1) issue all 7 x-loads (latency in flight), (2) warp 0 computes
// this plane's scale = hardsigmoid(w2[c,:].t[b,:] + b2[c]) UNDER those loads,
// (3) sync, multiply, stream out. w2/g_t are L2-resident broadcasts.
// Reverse plane order (L2-hot tail first); __ldcs / __stcs (stwt regressed).
// ---------------------------------------------------------------------------
__global__ void __launch_bounds__(T_) se_scale_kernel(const float* __restrict__ x,
                                                      const float* __restrict__ w2,
                                                      const float* __restrict__ b2,
                                                      float* __restrict__ out) {
    const int plane = (NPLANES_ - 1) - blockIdx.x;
    const int b = plane / C_;
    const int c = plane % C_;

    const float4* __restrict__ p =
        reinterpret_cast<const float4*>(x) + (size_t)plane * HW4_;
    float4* __restrict__ o =
        reinterpret_cast<float4*>(out) + (size_t)plane * HW4_;
    const int tid  = threadIdx.x;
    const int lane = tid & 31;
    const int wid  = tid >> 5;

    __shared__ float s_sc;

    // (1) Issue the plane's loads first — independent of the scale factor.
    float4 v[K_];
    #pragma unroll
    for (int k = 0; k < K_; k++)
        v[k] = __ldcs(&p[tid + k * T_]);

    // (2) Warp 0 computes the scale factor while the loads are in flight.
    if (wid == 0) {
        const float* __restrict__ wc = w2 + c * CR_;
        const float* __restrict__ tb = g_t + b * CR_;
        float acc = 0.0f;
        #pragma unroll
        for (int k = 0; k < 3; k++) {
            const int r = lane + 32 * k;
            acc = fmaf(__ldg(&wc[r]), tb[r], acc);
        }
        #pragma unroll
        for (int off = 16; off > 0; off >>= 1)
            acc += __shfl_down_sync(0xffffffffu, acc, off);
        if (lane == 0)
            s_sc = __saturatef(fmaf(acc + __ldg(&b2[c]), 1.0f / 6.0f, 0.5f));
    }
    __syncthreads();

    // (3) Multiply and stream out.
    const float sc = s_sc;
    #pragma unroll
    for (int k = 0; k < K_; k++) {
        v[k].x *= sc; v[k].y *= sc; v[k].z *= sc; v[k].w *= sc;
        __stcs(&o[tid + k * T_], v[k]);
    }
}

// ---------------------------------------------------------------------------
extern "C" void kernel_launch(void* const* d_in, const int* in_sizes, int n_in,
                              void* d_out, int out_size) {
    const float* x  = (const float*)d_in[0];
    const float* w1 = (const float*)d_in[1];
    const float* b1 = (const float*)d_in[2];
    const float* w2 = (const float*)d_in[3];
    const float* b2 = (const float*)d_in[4];
    float* out = (float*)d_out;

    se_reduce_kernel<<<NPLANES_, T_>>>(x);
    se_fc1_kernel<<<(B_ * CR_) / 4, 128>>>(w1, b1);
    se_scale_kernel<<<NPLANES_, T_>>>(x, w2, b2, out);
}